// round 2
// baseline (speedup 1.0000x reference)
#include <cuda_runtime.h>
#include <math.h>

typedef unsigned long long ull;

#define M_TOTAL 131072  // 2048 windows * 64 tokens

// Scratch (device globals: allocation-guard safe)
__device__ float g_qkv[(size_t)M_TOTAL * 768];   // (B*N, 3*C) qkv activations
__device__ float g_ao[(size_t)M_TOTAL * 256];    // attention output, (B*N, C)
__device__ float g_bias16[8 * 64 * 64];          // 16*sigmoid(rpb), (H, N, N)

// ---------- packed f32x2 helpers (FFMA2 path, 2x fp32 throughput) ----------
__device__ __forceinline__ ull f2pack(float lo, float hi) {
    ull d; asm("mov.b64 %0, {%1, %2};" : "=l"(d) : "f"(lo), "f"(hi)); return d;
}
__device__ __forceinline__ float2 f2unpack(ull v) {
    float2 r; asm("mov.b64 {%0, %1}, %2;" : "=f"(r.x), "=f"(r.y) : "l"(v)); return r;
}
__device__ __forceinline__ ull f2fma(ull a, ull b, ull c) {
    ull d; asm("fma.rn.f32x2 %0, %1, %2, %3;" : "=l"(d) : "l"(a), "l"(b), "l"(c)); return d;
}
__device__ __forceinline__ ull f2add(ull a, ull b) {
    ull d; asm("add.rn.f32x2 %0, %1, %2;" : "=l"(d) : "l"(a), "l"(b)); return d;
}

// ---------- prep: CPB MLP -> 16*sigmoid(relative position bias) ----------
__global__ void prep_kernel(const float* __restrict__ cpb_w1,
                            const float* __restrict__ cpb_b1,
                            const float* __restrict__ cpb_w2) {
    __shared__ float bt[225][8];
    const int t = threadIdx.x;
    if (t < 225) {
        int i = t / 15, j = t % 15;
        float t0 = (float)(i - 7) * (8.0f / 7.0f);
        float t1 = (float)(j - 7) * (8.0f / 7.0f);
        t0 = copysignf(log2f(fabsf(t0) + 1.0f), t0) * (1.0f / 3.0f);
        t1 = copysignf(log2f(fabsf(t1) + 1.0f), t1) * (1.0f / 3.0f);
        float acc[8];
#pragma unroll
        for (int hh = 0; hh < 8; hh++) acc[hh] = 0.0f;
        for (int u = 0; u < 512; u++) {
            float hu = cpb_w1[2 * u] * t0 + cpb_w1[2 * u + 1] * t1 + cpb_b1[u];
            hu = fmaxf(hu, 0.0f);
#pragma unroll
            for (int hh = 0; hh < 8; hh++) acc[hh] += cpb_w2[hh * 512 + u] * hu;
        }
#pragma unroll
        for (int hh = 0; hh < 8; hh++) bt[t][hh] = acc[hh];
    }
    __syncthreads();
    for (int idx = t; idx < 8 * 64 * 64; idx += 256) {
        int hh = idx >> 12;
        int n = (idx >> 6) & 63;
        int m = idx & 63;
        int rid = ((n >> 3) - (m >> 3) + 7) * 15 + ((n & 7) - (m & 7) + 7);
        float v = bt[rid][hh];
        g_bias16[idx] = 16.0f / (1.0f + __expf(-v));
    }
}

// ---------- generic 64x64x(K=256) fp32 GEMM, Y = A @ W^T + bias ----------
// MODE==1: A = Ap (x), Y = g_qkv, bias = [q_bias, 0, v_bias] (b0=q_bias, b1=v_bias)
// MODE==0: A = g_ao,   Y = Yp,    bias = b0
// smem stored k-major with xor swizzle: conflict-free transpose stores and
// conflict-free float4 reads. Inner loop: 8 FFMA2 + ~3 LDS-cycles per k per warp.
template <int MODE>
__global__ __launch_bounds__(256) void gemm64_kernel(
    const float* __restrict__ Ap, const float* __restrict__ W,
    const float* __restrict__ b0, const float* __restrict__ b1,
    float* __restrict__ Yp, int Ncols)
{
    const float* A = (MODE == 1) ? Ap : g_ao;
    float* Y = (MODE == 1) ? g_qkv : Yp;

    __shared__ __align__(16) float sA[32 * 64];
    __shared__ __align__(16) float sB[32 * 64];

    const int t = threadIdx.x;
    const int tr = t >> 4;       // 0..15 (row group)
    const int tc = t & 15;       // 0..15 (col group)
    const int bm = blockIdx.x * 64;
    const int bn = blockIdx.y * 64;

    ull acc[4][2];
#pragma unroll
    for (int i = 0; i < 4; i++) { acc[i][0] = 0ULL; acc[i][1] = 0ULL; }

    for (int k0 = 0; k0 < 256; k0 += 32) {
#pragma unroll
        for (int i = 0; i < 2; i++) {
            int idx = t + i * 256;         // 0..511
            int row = idx >> 3;            // 0..63
            int c4 = (idx & 7) << 2;       // 0,4,...,28
            float4 av = *(const float4*)(A + (size_t)(bm + row) * 256 + k0 + c4);
            float4 wv = *(const float4*)(W + (size_t)(bn + row) * 256 + k0 + c4);
            float va[4] = {av.x, av.y, av.z, av.w};
            float vw[4] = {wv.x, wv.y, wv.z, wv.w};
#pragma unroll
            for (int q = 0; q < 4; q++) {
                int k = c4 + q;
                int off = k * 64 + ((((row >> 2) ^ (k >> 2)) & 15) << 2) + (row & 3);
                sA[off] = va[q];
                sB[off] = vw[q];
            }
        }
        __syncthreads();
#pragma unroll
        for (int k = 0; k < 32; k++) {
            int sw = k >> 2;
            float4 av = *(const float4*)(sA + k * 64 + (((tr ^ sw) & 15) << 2));
            ulonglong2 bv = *(const ulonglong2*)(sB + k * 64 + (((tc ^ sw) & 15) << 2));
            ull a0 = f2pack(av.x, av.x);
            ull a1 = f2pack(av.y, av.y);
            ull a2 = f2pack(av.z, av.z);
            ull a3 = f2pack(av.w, av.w);
            acc[0][0] = f2fma(a0, bv.x, acc[0][0]);
            acc[0][1] = f2fma(a0, bv.y, acc[0][1]);
            acc[1][0] = f2fma(a1, bv.x, acc[1][0]);
            acc[1][1] = f2fma(a1, bv.y, acc[1][1]);
            acc[2][0] = f2fma(a2, bv.x, acc[2][0]);
            acc[2][1] = f2fma(a2, bv.y, acc[2][1]);
            acc[3][0] = f2fma(a3, bv.x, acc[3][0]);
            acc[3][1] = f2fma(a3, bv.y, acc[3][1]);
        }
        __syncthreads();
    }

    const int col0 = bn + (tc << 2);
    float bias[4];
#pragma unroll
    for (int q = 0; q < 4; q++) {
        int cidx = col0 + q;
        if (MODE == 1) {
            bias[q] = (cidx < 256) ? b0[cidx] : ((cidx < 512) ? 0.0f : b1[cidx - 512]);
        } else {
            bias[q] = b0[cidx];
        }
    }
#pragma unroll
    for (int i = 0; i < 4; i++) {
        size_t row = (size_t)(bm + (tr << 2) + i);
        float2 p0 = f2unpack(acc[i][0]);
        float2 p1 = f2unpack(acc[i][1]);
        float4 o = make_float4(p0.x + bias[0], p0.y + bias[1], p1.x + bias[2], p1.y + bias[3]);
        *(float4*)(Y + row * (size_t)Ncols + col0) = o;
    }
}

// ---------- attention: one block per (window b, head h) ----------
__global__ __launch_bounds__(256) void attn_kernel(const float* __restrict__ logit_scale) {
    const int b = blockIdx.x;
    const int h = blockIdx.y;
    __shared__ __align__(16) float sq[64 * 36];
    __shared__ __align__(16) float sk[64 * 36];
    __shared__ __align__(16) float sv[64 * 36];
    __shared__ float s_scale;
    const int t = threadIdx.x;

    const float* base = g_qkv + (size_t)b * (64 * 768) + h * 32;
#pragma unroll
    for (int i = 0; i < 2; i++) {
        int idx = t + i * 256;
        int n = idx >> 3;
        int d4 = (idx & 7) << 2;
        const float* rb = base + n * 768 + d4;
        float4 qv = *(const float4*)(rb);
        float4 kv = *(const float4*)(rb + 256);
        float4 vv = *(const float4*)(rb + 512);
        *(float4*)(sq + n * 36 + d4) = qv;
        *(float4*)(sk + n * 36 + d4) = kv;
        *(float4*)(sv + n * 36 + d4) = vv;
    }
    if (t == 0) s_scale = __expf(fminf(logit_scale[h], 4.6051702f));  // min(ls, log(100))
    __syncthreads();

    // normalize q (fold in logit scale) and k rows
    if (t < 128) {
        float* row = (t < 64) ? (sq + t * 36) : (sk + (t - 64) * 36);
        float s = 0.0f;
#pragma unroll
        for (int d = 0; d < 32; d++) s += row[d] * row[d];
        float inv = 1.0f / fmaxf(sqrtf(s), 1e-12f);
        if (t < 64) inv *= s_scale;
#pragma unroll
        for (int d = 0; d < 32; d++) row[d] *= inv;
    }
    __syncthreads();

    const int n = t >> 2;   // row 0..63 (4 threads per row)
    const int c = t & 3;

    ull qr[16];
    {
        const float* qrow = sq + n * 36;
#pragma unroll
        for (int i = 0; i < 8; i++) {
            ulonglong2 qv = *(const ulonglong2*)(qrow + i * 4);
            qr[2 * i] = qv.x;
            qr[2 * i + 1] = qv.y;
        }
    }

    const float* bias = g_bias16 + ((h * 64 + n) * 64);
    float scr[16];
#pragma unroll
    for (int j = 0; j < 16; j++) {
        int m = (j << 2) + c;
        const float* krow = sk + m * 36;
        ull acc0 = 0ULL, acc1 = 0ULL;
#pragma unroll
        for (int i = 0; i < 8; i++) {
            ulonglong2 kv = *(const ulonglong2*)(krow + i * 4);
            acc0 = f2fma(qr[2 * i], kv.x, acc0);
            acc1 = f2fma(qr[2 * i + 1], kv.y, acc1);
        }
        float2 a0 = f2unpack(acc0);
        float2 a1 = f2unpack(acc1);
        scr[j] = a0.x + a0.y + a1.x + a1.y + bias[m];
    }

    // softmax over 64 columns (16 regs x 4 threads)
    float mx = scr[0];
#pragma unroll
    for (int j = 1; j < 16; j++) mx = fmaxf(mx, scr[j]);
    mx = fmaxf(mx, __shfl_xor_sync(0xffffffffu, mx, 1));
    mx = fmaxf(mx, __shfl_xor_sync(0xffffffffu, mx, 2));
    float sum = 0.0f;
#pragma unroll
    for (int j = 0; j < 16; j++) { scr[j] = __expf(scr[j] - mx); sum += scr[j]; }
    sum += __shfl_xor_sync(0xffffffffu, sum, 1);
    sum += __shfl_xor_sync(0xffffffffu, sum, 2);
    float rs = 1.0f / sum;
#pragma unroll
    for (int j = 0; j < 16; j++) scr[j] *= rs;

    // out[n][:] = sum_m attn[n][m] * v[m][:]
    ull oacc[16];
#pragma unroll
    for (int i = 0; i < 16; i++) oacc[i] = 0ULL;
#pragma unroll
    for (int j = 0; j < 16; j++) {
        int m = (j << 2) + c;
        ull p = f2pack(scr[j], scr[j]);
        const float* vrow = sv + m * 36;
#pragma unroll
        for (int i = 0; i < 8; i++) {
            ulonglong2 vv = *(const ulonglong2*)(vrow + i * 4);
            oacc[2 * i] = f2fma(p, vv.x, oacc[2 * i]);
            oacc[2 * i + 1] = f2fma(p, vv.y, oacc[2 * i + 1]);
        }
    }
#pragma unroll
    for (int i = 0; i < 16; i++) {
        oacc[i] = f2add(oacc[i], __shfl_xor_sync(0xffffffffu, oacc[i], 1));
        oacc[i] = f2add(oacc[i], __shfl_xor_sync(0xffffffffu, oacc[i], 2));
    }

    // write: thread c owns d in [c*8, c*8+8)
    float* orow = g_ao + (size_t)(b * 64 + n) * 256 + h * 32 + c * 8;
    ulonglong2 w0, w1;
    w0.x = oacc[c * 4 + 0]; w0.y = oacc[c * 4 + 1];
    w1.x = oacc[c * 4 + 2]; w1.y = oacc[c * 4 + 3];
    *(ulonglong2*)(orow) = w0;
    *(ulonglong2*)(orow + 4) = w1;
}

extern "C" void kernel_launch(void* const* d_in, const int* in_sizes, int n_in,
                              void* d_out, int out_size) {
    const float* x           = (const float*)d_in[0];
    const float* qkv_w       = (const float*)d_in[1];
    const float* q_bias      = (const float*)d_in[2];
    const float* v_bias      = (const float*)d_in[3];
    const float* logit_scale = (const float*)d_in[4];
    const float* cpb_w1      = (const float*)d_in[5];
    const float* cpb_b1      = (const float*)d_in[6];
    const float* cpb_w2      = (const float*)d_in[7];
    const float* proj_w      = (const float*)d_in[8];
    const float* proj_b      = (const float*)d_in[9];
    float* out = (float*)d_out;

    prep_kernel<<<1, 256>>>(cpb_w1, cpb_b1, cpb_w2);
    gemm64_kernel<1><<<dim3(M_TOTAL / 64, 12), 256>>>(x, qkv_w, q_bias, v_bias, nullptr, 768);
    attn_kernel<<<dim3(2048, 8), 256>>>(logit_scale);
    gemm64_kernel<0><<<dim3(M_TOTAL / 64, 4), 256>>>(nullptr, proj_w, proj_b, nullptr, out, 256);
}

// round 4
// speedup vs baseline: 1.7228x; 1.7228x over previous
#include <cuda_runtime.h>
#include <cuda_bf16.h>
#include <math.h>
#include <stdint.h>

typedef unsigned long long ull;
#define M_TOTAL 131072  // 2048 windows * 64 tokens

// ---------------- scratch (device globals) ----------------
__device__ float         g_qkv[(size_t)M_TOTAL * 768];   // fp32 qkv (q|k|v)
__device__ __nv_bfloat16 g_a1[(size_t)M_TOTAL * 768];    // x split [hi|lo|hi]
__device__ __nv_bfloat16 g_a2[(size_t)M_TOTAL * 768];    // attn-out split [hi|lo|hi]
__device__ __nv_bfloat16 g_wq[768 * 768];                // qkv_w split [hi|hi|lo]
__device__ __nv_bfloat16 g_wp[256 * 768];                // proj_w split [hi|hi|lo]
__device__ float         g_bias16[8 * 64 * 64];          // 16*sigmoid(rpb)
__device__ float         g_qkvbias[768];                 // [q_bias | 0 | v_bias]

// ---------------- f32x2 helpers ----------------
__device__ __forceinline__ ull f2pack(float lo, float hi) {
    ull d; asm("mov.b64 %0, {%1, %2};" : "=l"(d) : "f"(lo), "f"(hi)); return d;
}
__device__ __forceinline__ float2 f2unpack(ull v) {
    float2 r; asm("mov.b64 {%0, %1}, %2;" : "=f"(r.x), "=f"(r.y) : "l"(v)); return r;
}
__device__ __forceinline__ ull f2fma(ull a, ull b, ull c) {
    ull d; asm("fma.rn.f32x2 %0, %1, %2, %3;" : "=l"(d) : "l"(a), "l"(b), "l"(c)); return d;
}
__device__ __forceinline__ ull f2add(ull a, ull b) {
    ull d; asm("add.rn.f32x2 %0, %1, %2;" : "=l"(d) : "l"(a), "l"(b)); return d;
}

// ---------------- PTX helpers (all baseline ISA, no arch-feature gating) ----
__device__ __forceinline__ uint32_t smem_u32(const void* p) {
    uint32_t a;
    asm("{ .reg .u64 t; cvta.to.shared.u64 t, %1; cvt.u32.u64 %0, t; }" : "=r"(a) : "l"(p));
    return a;
}

#define CP_ASYNC16(dst, src) \
    asm volatile("cp.async.cg.shared.global [%0], [%1], 16;" :: "r"((uint32_t)(dst)), "l"(src))
#define CP_COMMIT() asm volatile("cp.async.commit_group;" ::: "memory")
#define CP_WAIT(n)  asm volatile("cp.async.wait_group %0;" :: "n"(n) : "memory")

#define LDSM_X4(r, addr) \
    asm volatile("ldmatrix.sync.aligned.m8n8.x4.shared.b16 {%0,%1,%2,%3}, [%4];" \
                 : "=r"((r)[0]), "=r"((r)[1]), "=r"((r)[2]), "=r"((r)[3]) : "r"(addr))

#define MMA16816(c, a, b0, b1) \
    asm volatile("mma.sync.aligned.m16n8k16.row.col.f32.bf16.bf16.f32 " \
                 "{%0,%1,%2,%3}, {%4,%5,%6,%7}, {%8,%9}, {%0,%1,%2,%3};" \
                 : "+f"((c)[0]), "+f"((c)[1]), "+f"((c)[2]), "+f"((c)[3]) \
                 : "r"((a)[0]), "r"((a)[1]), "r"((a)[2]), "r"((a)[3]), "r"(b0), "r"(b1))

__device__ __forceinline__ void split2(float v, unsigned short& h, unsigned short& l) {
    __nv_bfloat16 hb = __float2bfloat16_rn(v);
    float r = v - __bfloat162float(hb);
    __nv_bfloat16 lb = __float2bfloat16_rn(r);
    h = *(unsigned short*)&hb;
    l = *(unsigned short*)&lb;
}

// ---------------- prep: CPB MLP bias + qkv bias vector ----------------
__global__ void prep_kernel(const float* __restrict__ cpb_w1,
                            const float* __restrict__ cpb_b1,
                            const float* __restrict__ cpb_w2,
                            const float* __restrict__ q_bias,
                            const float* __restrict__ v_bias) {
    __shared__ float bt[225][8];
    const int t = threadIdx.x;
    for (int i = t; i < 768; i += 256)
        g_qkvbias[i] = (i < 256) ? q_bias[i] : ((i < 512) ? 0.0f : v_bias[i - 512]);
    if (t < 225) {
        int i = t / 15, j = t % 15;
        float t0 = (float)(i - 7) * (8.0f / 7.0f);
        float t1 = (float)(j - 7) * (8.0f / 7.0f);
        t0 = copysignf(log2f(fabsf(t0) + 1.0f), t0) * (1.0f / 3.0f);
        t1 = copysignf(log2f(fabsf(t1) + 1.0f), t1) * (1.0f / 3.0f);
        float acc[8];
#pragma unroll
        for (int hh = 0; hh < 8; hh++) acc[hh] = 0.0f;
        for (int u = 0; u < 512; u++) {
            float hu = fmaxf(cpb_w1[2 * u] * t0 + cpb_w1[2 * u + 1] * t1 + cpb_b1[u], 0.0f);
#pragma unroll
            for (int hh = 0; hh < 8; hh++) acc[hh] += cpb_w2[hh * 512 + u] * hu;
        }
#pragma unroll
        for (int hh = 0; hh < 8; hh++) bt[t][hh] = acc[hh];
    }
    __syncthreads();
    for (int idx = t; idx < 8 * 64 * 64; idx += 256) {
        int hh = idx >> 12, n = (idx >> 6) & 63, m = idx & 63;
        int rid = ((n >> 3) - (m >> 3) + 7) * 15 + ((n & 7) - (m & 7) + 7);
        g_bias16[idx] = 16.0f / (1.0f + __expf(-bt[rid][hh]));
    }
}

// ---------------- split activations x -> g_a1 [hi|lo|hi] ----------------
__global__ __launch_bounds__(256) void split_act(const float* __restrict__ x) {
    size_t u = ((size_t)blockIdx.x * 256 + threadIdx.x) * 4;
    size_t row = u >> 8;
    int col = (int)(u & 255);
    float4 v = *(const float4*)(x + u);
    unsigned short h[4], l[4];
    split2(v.x, h[0], l[0]); split2(v.y, h[1], l[1]);
    split2(v.z, h[2], l[2]); split2(v.w, h[3], l[3]);
    uint2 hv, lv;
    hv.x = (uint32_t)h[0] | ((uint32_t)h[1] << 16);
    hv.y = (uint32_t)h[2] | ((uint32_t)h[3] << 16);
    lv.x = (uint32_t)l[0] | ((uint32_t)l[1] << 16);
    lv.y = (uint32_t)l[2] | ((uint32_t)l[3] << 16);
    __nv_bfloat16* d = g_a1 + row * 768 + col;
    *(uint2*)d = hv;
    *(uint2*)(d + 256) = lv;
    *(uint2*)(d + 512) = hv;
}

// ---------------- split weights -> [hi|hi|lo] ----------------
template <int WHICH>  // 0: qkv_w (768 rows) -> g_wq ; 1: proj_w (256 rows) -> g_wp
__global__ __launch_bounds__(256) void split_w(const float* __restrict__ w) {
    __nv_bfloat16* dst = (WHICH == 0) ? g_wq : g_wp;
    size_t u = ((size_t)blockIdx.x * 256 + threadIdx.x) * 4;
    size_t row = u >> 8;
    int col = (int)(u & 255);
    float4 v = *(const float4*)(w + u);
    unsigned short h[4], l[4];
    split2(v.x, h[0], l[0]); split2(v.y, h[1], l[1]);
    split2(v.z, h[2], l[2]); split2(v.w, h[3], l[3]);
    uint2 hv, lv;
    hv.x = (uint32_t)h[0] | ((uint32_t)h[1] << 16);
    hv.y = (uint32_t)h[2] | ((uint32_t)h[3] << 16);
    lv.x = (uint32_t)l[0] | ((uint32_t)l[1] << 16);
    lv.y = (uint32_t)l[2] | ((uint32_t)l[3] << 16);
    __nv_bfloat16* d = dst + row * 768 + col;
    *(uint2*)d = hv;
    *(uint2*)(d + 256) = hv;
    *(uint2*)(d + 512) = lv;
}

// ---------------- mma.sync bf16 GEMM: C[M,N] = A'[M,768] @ W'[N,768]^T + bias -----
// MODE 0: A=g_a1, W=g_wq, C=g_qkv (ldc=768, 6 N-blocks)
// MODE 1: A=g_a2, W=g_wp, C=c_ext (ldc=256, 2 N-blocks)
// Block tile 128x128, K chunks of 64, 2-stage cp.async double buffer.
// smem layout per chunk: 128 rows x 128B, 16B chunk permutation c16^=(row&7)
// -> conflict-free cp.async stores and ldmatrix reads.
template <int MODE>
__global__ __launch_bounds__(256) void mma_gemm(const float* __restrict__ bias_ext,
                                                float* __restrict__ c_ext) {
    const __nv_bfloat16* A = (MODE == 0) ? g_a1 : g_a2;
    const __nv_bfloat16* W = (MODE == 0) ? g_wq : g_wp;
    const float* bias = (MODE == 0) ? g_qkvbias : bias_ext;
    float* C = (MODE == 0) ? g_qkv : c_ext;
    const int ldc = (MODE == 0) ? 768 : 256;

    extern __shared__ __align__(128) char smem[];
    const uint32_t sbase = smem_u32(smem);
    const int t = threadIdx.x;
    const int lane = t & 31, wid = t >> 5;
    const int bn = blockIdx.x * 128;
    const size_t bm = (size_t)blockIdx.y * 128;
    const int wm = (wid >> 2) * 64;  // warp row: 0 / 64
    const int wn = (wid & 3) * 32;   // warp col: 0..96

    const __nv_bfloat16* Ag = A + bm * 768;
    const __nv_bfloat16* Wg = W + (size_t)bn * 768;

    auto load_chunk = [&](int c, int s) {
        uint32_t ab = sbase + s * 32768;
        uint32_t bb = ab + 16384;
        const char* Ap = (const char*)(Ag + c * 64);
        const char* Bp = (const char*)(Wg + c * 64);
#pragma unroll
        for (int i = 0; i < 4; i++) {
            int u = i * 256 + t;  // 0..1023
            int row = u >> 3;     // 0..127
            int c16 = u & 7;
            uint32_t off = (uint32_t)(row * 128 + ((c16 ^ (row & 7)) << 4));
            CP_ASYNC16(ab + off, Ap + (size_t)row * 1536 + c16 * 16);
            CP_ASYNC16(bb + off, Bp + (size_t)row * 1536 + c16 * 16);
        }
    };

    float acc[4][4][4];
#pragma unroll
    for (int mi = 0; mi < 4; mi++)
#pragma unroll
        for (int ni = 0; ni < 4; ni++)
#pragma unroll
            for (int q = 0; q < 4; q++) acc[mi][ni][q] = 0.0f;

    load_chunk(0, 0);
    CP_COMMIT();

    for (int c = 0; c < 12; c++) {
        if (c + 1 < 12) {
            load_chunk(c + 1, (c + 1) & 1);
            CP_COMMIT();
            CP_WAIT(1);
        } else {
            CP_WAIT(0);
        }
        __syncthreads();
        uint32_t ab = sbase + (c & 1) * 32768;
        uint32_t bb = ab + 16384;
#pragma unroll
        for (int ks = 0; ks < 4; ks++) {
            const int kc = ks * 2;  // 16B-chunk index of this k16 step
            uint32_t a_regs[4][4];
#pragma unroll
            for (int mi = 0; mi < 4; mi++) {
                int r = wm + mi * 16 + (lane & 15);
                int kk = kc + (lane >> 4);
                uint32_t addr = ab + r * 128 + ((kk ^ (r & 7)) << 4);
                LDSM_X4(a_regs[mi], addr);
            }
            uint32_t b_regs[2][4];
#pragma unroll
            for (int np = 0; np < 2; np++) {
                int r = wn + np * 16 + (lane & 15);
                int kk = kc + (lane >> 4);
                uint32_t addr = bb + r * 128 + ((kk ^ (r & 7)) << 4);
                LDSM_X4(b_regs[np], addr);
            }
#pragma unroll
            for (int mi = 0; mi < 4; mi++)
#pragma unroll
                for (int ni = 0; ni < 4; ni++) {
                    uint32_t b0 = b_regs[ni >> 1][ni & 1];
                    uint32_t b1 = b_regs[ni >> 1][(ni & 1) + 2];
                    MMA16816(acc[mi][ni], a_regs[mi], b0, b1);
                }
        }
        __syncthreads();
    }

    // epilogue: c0,c1 -> row g cols 2t,2t+1 ; c2,c3 -> row g+8
    const int g = lane >> 2, tt = lane & 3;
#pragma unroll
    for (int mi = 0; mi < 4; mi++) {
        size_t r0 = bm + wm + mi * 16 + g;
#pragma unroll
        for (int ni = 0; ni < 4; ni++) {
            int col = bn + wn + ni * 8 + tt * 2;
            float bv0 = bias[col], bv1 = bias[col + 1];
            float2 v0 = make_float2(acc[mi][ni][0] + bv0, acc[mi][ni][1] + bv1);
            float2 v1 = make_float2(acc[mi][ni][2] + bv0, acc[mi][ni][3] + bv1);
            *(float2*)(C + r0 * ldc + col) = v0;
            *(float2*)(C + (r0 + 8) * ldc + col) = v1;
        }
    }
}

// ---------------- attention: one block per (window, head) ----------------
__global__ __launch_bounds__(256) void attn_kernel(const float* __restrict__ logit_scale) {
    const int b = blockIdx.x;
    const int h = blockIdx.y;
    __shared__ __align__(16) float sq[64 * 36];
    __shared__ __align__(16) float sk[64 * 36];
    __shared__ __align__(16) float sv[64 * 36];
    __shared__ float s_scale;
    const int t = threadIdx.x;

    const float* base = g_qkv + (size_t)b * (64 * 768) + h * 32;
#pragma unroll
    for (int i = 0; i < 2; i++) {
        int idx = t + i * 256;
        int n = idx >> 3;
        int d4 = (idx & 7) << 2;
        const float* rb = base + n * 768 + d4;
        float4 qv = *(const float4*)(rb);
        float4 kv = *(const float4*)(rb + 256);
        float4 vv = *(const float4*)(rb + 512);
        *(float4*)(sq + n * 36 + d4) = qv;
        *(float4*)(sk + n * 36 + d4) = kv;
        *(float4*)(sv + n * 36 + d4) = vv;
    }
    if (t == 0) s_scale = __expf(fminf(logit_scale[h], 4.6051702f));
    __syncthreads();

    if (t < 128) {
        float* row = (t < 64) ? (sq + t * 36) : (sk + (t - 64) * 36);
        float s = 0.0f;
#pragma unroll
        for (int d = 0; d < 32; d++) s += row[d] * row[d];
        float inv = 1.0f / fmaxf(sqrtf(s), 1e-12f);
        if (t < 64) inv *= s_scale;
#pragma unroll
        for (int d = 0; d < 32; d++) row[d] *= inv;
    }
    __syncthreads();

    const int n = t >> 2;
    const int c = t & 3;

    ull qr[16];
    {
        const float* qrow = sq + n * 36;
#pragma unroll
        for (int i = 0; i < 8; i++) {
            ulonglong2 qv = *(const ulonglong2*)(qrow + i * 4);
            qr[2 * i] = qv.x;
            qr[2 * i + 1] = qv.y;
        }
    }

    const float* bias = g_bias16 + ((h * 64 + n) * 64);
    float scr[16];
#pragma unroll
    for (int j = 0; j < 16; j++) {
        int m = (j << 2) + c;
        const float* krow = sk + m * 36;
        ull acc0 = 0ULL, acc1 = 0ULL;
#pragma unroll
        for (int i = 0; i < 8; i++) {
            ulonglong2 kv = *(const ulonglong2*)(krow + i * 4);
            acc0 = f2fma(qr[2 * i], kv.x, acc0);
            acc1 = f2fma(qr[2 * i + 1], kv.y, acc1);
        }
        float2 a0 = f2unpack(acc0);
        float2 a1 = f2unpack(acc1);
        scr[j] = a0.x + a0.y + a1.x + a1.y + bias[m];
    }

    float mx = scr[0];
#pragma unroll
    for (int j = 1; j < 16; j++) mx = fmaxf(mx, scr[j]);
    mx = fmaxf(mx, __shfl_xor_sync(0xffffffffu, mx, 1));
    mx = fmaxf(mx, __shfl_xor_sync(0xffffffffu, mx, 2));
    float sum = 0.0f;
#pragma unroll
    for (int j = 0; j < 16; j++) { scr[j] = __expf(scr[j] - mx); sum += scr[j]; }
    sum += __shfl_xor_sync(0xffffffffu, sum, 1);
    sum += __shfl_xor_sync(0xffffffffu, sum, 2);
    float rs = 1.0f / sum;
#pragma unroll
    for (int j = 0; j < 16; j++) scr[j] *= rs;

    ull oacc[16];
#pragma unroll
    for (int i = 0; i < 16; i++) oacc[i] = 0ULL;
#pragma unroll
    for (int j = 0; j < 16; j++) {
        int m = (j << 2) + c;
        ull p = f2pack(scr[j], scr[j]);
        const float* vrow = sv + m * 36;
#pragma unroll
        for (int i = 0; i < 8; i++) {
            ulonglong2 vv = *(const ulonglong2*)(vrow + i * 4);
            oacc[2 * i] = f2fma(p, vv.x, oacc[2 * i]);
            oacc[2 * i + 1] = f2fma(p, vv.y, oacc[2 * i + 1]);
        }
    }
#pragma unroll
    for (int i = 0; i < 16; i++) {
        oacc[i] = f2add(oacc[i], __shfl_xor_sync(0xffffffffu, oacc[i], 1));
        oacc[i] = f2add(oacc[i], __shfl_xor_sync(0xffffffffu, oacc[i], 2));
    }

    // write bf16 hi/lo split directly (feeds proj GEMM): thread owns cols [c*8, c*8+8)
    float vals[8];
#pragma unroll
    for (int i = 0; i < 4; i++) {
        float2 p = f2unpack(oacc[c * 4 + i]);
        vals[2 * i] = p.x;
        vals[2 * i + 1] = p.y;
    }
    unsigned short hi[8], lo[8];
#pragma unroll
    for (int i = 0; i < 8; i++) split2(vals[i], hi[i], lo[i]);
    uint4 hv, lv;
    hv.x = (uint32_t)hi[0] | ((uint32_t)hi[1] << 16);
    hv.y = (uint32_t)hi[2] | ((uint32_t)hi[3] << 16);
    hv.z = (uint32_t)hi[4] | ((uint32_t)hi[5] << 16);
    hv.w = (uint32_t)hi[6] | ((uint32_t)hi[7] << 16);
    lv.x = (uint32_t)lo[0] | ((uint32_t)lo[1] << 16);
    lv.y = (uint32_t)lo[2] | ((uint32_t)lo[3] << 16);
    lv.z = (uint32_t)lo[4] | ((uint32_t)lo[5] << 16);
    lv.w = (uint32_t)lo[6] | ((uint32_t)lo[7] << 16);
    __nv_bfloat16* orow = g_a2 + (size_t)(b * 64 + n) * 768 + h * 32 + c * 8;
    *(uint4*)orow = hv;
    *(uint4*)(orow + 256) = lv;
    *(uint4*)(orow + 512) = hv;
}

extern "C" void kernel_launch(void* const* d_in, const int* in_sizes, int n_in,
                              void* d_out, int out_size) {
    const float* x           = (const float*)d_in[0];
    const float* qkv_w       = (const float*)d_in[1];
    const float* q_bias      = (const float*)d_in[2];
    const float* v_bias      = (const float*)d_in[3];
    const float* logit_scale = (const float*)d_in[4];
    const float* cpb_w1      = (const float*)d_in[5];
    const float* cpb_b1      = (const float*)d_in[6];
    const float* cpb_w2      = (const float*)d_in[7];
    const float* proj_w      = (const float*)d_in[8];
    const float* proj_b      = (const float*)d_in[9];
    float* out = (float*)d_out;

    const int SMEM_BYTES = 2 * 32768;  // 64 KB double buffer
    cudaFuncSetAttribute(mma_gemm<0>, cudaFuncAttributeMaxDynamicSharedMemorySize, SMEM_BYTES);
    cudaFuncSetAttribute(mma_gemm<1>, cudaFuncAttributeMaxDynamicSharedMemorySize, SMEM_BYTES);

    prep_kernel<<<1, 256>>>(cpb_w1, cpb_b1, cpb_w2, q_bias, v_bias);
    split_act<<<M_TOTAL * 256 / 4 / 256, 256>>>(x);
    split_w<0><<<768 * 256 / 4 / 256, 256>>>(qkv_w);
    split_w<1><<<256 * 256 / 4 / 256, 256>>>(proj_w);
    mma_gemm<0><<<dim3(6, M_TOTAL / 128), 256, SMEM_BYTES>>>(nullptr, nullptr);
    attn_kernel<<<dim3(2048, 8), 256>>>(logit_scale);
    mma_gemm<1><<<dim3(2, M_TOTAL / 128), 256, SMEM_BYTES>>>(proj_b, out);
}

// round 5
// speedup vs baseline: 2.2996x; 1.3348x over previous
#include <cuda_runtime.h>
#include <cuda_bf16.h>
#include <math.h>
#include <stdint.h>

#define M_TOTAL 131072  // 2048 windows * 64 tokens

// ---------------- scratch (device globals) ----------------
__device__ float         g_qkv[(size_t)M_TOTAL * 768];   // fp32 qkv (q|k|v)
__device__ __nv_bfloat16 g_a1[(size_t)M_TOTAL * 768];    // x split [hi|lo|hi]
__device__ __nv_bfloat16 g_a2[(size_t)M_TOTAL * 768];    // attn-out split [hi|lo|hi]
__device__ __nv_bfloat16 g_wq[768 * 768];                // qkv_w split [hi|hi|lo]
__device__ __nv_bfloat16 g_wp[256 * 768];                // proj_w split [hi|hi|lo]
__device__ float         g_bias16[8 * 64 * 64];          // 16*sigmoid(rpb)
__device__ float         g_qkvbias[768];                 // [q_bias | 0 | v_bias]

// ---------------- PTX helpers (baseline ISA only) ----------------
__device__ __forceinline__ uint32_t smem_u32(const void* p) {
    uint32_t a;
    asm("{ .reg .u64 t; cvta.to.shared.u64 t, %1; cvt.u32.u64 %0, t; }" : "=r"(a) : "l"(p));
    return a;
}

#define CP_ASYNC16(dst, src) \
    asm volatile("cp.async.cg.shared.global [%0], [%1], 16;" :: "r"((uint32_t)(dst)), "l"(src))
#define CP_COMMIT() asm volatile("cp.async.commit_group;" ::: "memory")
#define CP_WAIT(n)  asm volatile("cp.async.wait_group %0;" :: "n"(n) : "memory")

#define LDSM_X4(r, addr) \
    asm volatile("ldmatrix.sync.aligned.m8n8.x4.shared.b16 {%0,%1,%2,%3}, [%4];" \
                 : "=r"((r)[0]), "=r"((r)[1]), "=r"((r)[2]), "=r"((r)[3]) : "r"(addr))

#define MMA16816(c, a, b0, b1) \
    asm volatile("mma.sync.aligned.m16n8k16.row.col.f32.bf16.bf16.f32 " \
                 "{%0,%1,%2,%3}, {%4,%5,%6,%7}, {%8,%9}, {%0,%1,%2,%3};" \
                 : "+f"((c)[0]), "+f"((c)[1]), "+f"((c)[2]), "+f"((c)[3]) \
                 : "r"((a)[0]), "r"((a)[1]), "r"((a)[2]), "r"((a)[3]), "r"(b0), "r"(b1))

__device__ __forceinline__ void split2(float v, unsigned short& h, unsigned short& l) {
    __nv_bfloat16 hb = __float2bfloat16_rn(v);
    float r = v - __bfloat162float(hb);
    __nv_bfloat16 lb = __float2bfloat16_rn(r);
    h = *(unsigned short*)&hb;
    l = *(unsigned short*)&lb;
}

// pack two fp32 into one u32 of bf16x2: lo = a, hi = b
__device__ __forceinline__ uint32_t bf16x2_of(float a, float b) {
    uint32_t r;
    asm("cvt.rn.bf16x2.f32 %0, %1, %2;" : "=r"(r) : "f"(b), "f"(a));
    return r;
}

// ---------------- prep: CPB MLP bias + qkv bias vector ----------------
__global__ void prep_kernel(const float* __restrict__ cpb_w1,
                            const float* __restrict__ cpb_b1,
                            const float* __restrict__ cpb_w2,
                            const float* __restrict__ q_bias,
                            const float* __restrict__ v_bias) {
    __shared__ float bt[225][8];
    const int t = threadIdx.x;
    for (int i = t; i < 768; i += 256)
        g_qkvbias[i] = (i < 256) ? q_bias[i] : ((i < 512) ? 0.0f : v_bias[i - 512]);
    if (t < 225) {
        int i = t / 15, j = t % 15;
        float t0 = (float)(i - 7) * (8.0f / 7.0f);
        float t1 = (float)(j - 7) * (8.0f / 7.0f);
        t0 = copysignf(log2f(fabsf(t0) + 1.0f), t0) * (1.0f / 3.0f);
        t1 = copysignf(log2f(fabsf(t1) + 1.0f), t1) * (1.0f / 3.0f);
        float acc[8];
#pragma unroll
        for (int hh = 0; hh < 8; hh++) acc[hh] = 0.0f;
        for (int u = 0; u < 512; u++) {
            float hu = fmaxf(cpb_w1[2 * u] * t0 + cpb_w1[2 * u + 1] * t1 + cpb_b1[u], 0.0f);
#pragma unroll
            for (int hh = 0; hh < 8; hh++) acc[hh] += cpb_w2[hh * 512 + u] * hu;
        }
#pragma unroll
        for (int hh = 0; hh < 8; hh++) bt[t][hh] = acc[hh];
    }
    __syncthreads();
    for (int idx = t; idx < 8 * 64 * 64; idx += 256) {
        int hh = idx >> 12, n = (idx >> 6) & 63, m = idx & 63;
        int rid = ((n >> 3) - (m >> 3) + 7) * 15 + ((n & 7) - (m & 7) + 7);
        g_bias16[idx] = 16.0f / (1.0f + __expf(-bt[rid][hh]));
    }
}

// ---------------- split activations x -> g_a1 [hi|lo|hi] ----------------
__global__ __launch_bounds__(256) void split_act(const float* __restrict__ x) {
    size_t u = ((size_t)blockIdx.x * 256 + threadIdx.x) * 4;
    size_t row = u >> 8;
    int col = (int)(u & 255);
    float4 v = *(const float4*)(x + u);
    unsigned short h[4], l[4];
    split2(v.x, h[0], l[0]); split2(v.y, h[1], l[1]);
    split2(v.z, h[2], l[2]); split2(v.w, h[3], l[3]);
    uint2 hv, lv;
    hv.x = (uint32_t)h[0] | ((uint32_t)h[1] << 16);
    hv.y = (uint32_t)h[2] | ((uint32_t)h[3] << 16);
    lv.x = (uint32_t)l[0] | ((uint32_t)l[1] << 16);
    lv.y = (uint32_t)l[2] | ((uint32_t)l[3] << 16);
    __nv_bfloat16* d = g_a1 + row * 768 + col;
    *(uint2*)d = hv;
    *(uint2*)(d + 256) = lv;
    *(uint2*)(d + 512) = hv;
}

// ---------------- split weights -> [hi|hi|lo] ----------------
template <int WHICH>
__global__ __launch_bounds__(256) void split_w(const float* __restrict__ w) {
    __nv_bfloat16* dst = (WHICH == 0) ? g_wq : g_wp;
    size_t u = ((size_t)blockIdx.x * 256 + threadIdx.x) * 4;
    size_t row = u >> 8;
    int col = (int)(u & 255);
    float4 v = *(const float4*)(w + u);
    unsigned short h[4], l[4];
    split2(v.x, h[0], l[0]); split2(v.y, h[1], l[1]);
    split2(v.z, h[2], l[2]); split2(v.w, h[3], l[3]);
    uint2 hv, lv;
    hv.x = (uint32_t)h[0] | ((uint32_t)h[1] << 16);
    hv.y = (uint32_t)h[2] | ((uint32_t)h[3] << 16);
    lv.x = (uint32_t)l[0] | ((uint32_t)l[1] << 16);
    lv.y = (uint32_t)l[2] | ((uint32_t)l[3] << 16);
    __nv_bfloat16* d = dst + row * 768 + col;
    *(uint2*)d = hv;
    *(uint2*)(d + 256) = hv;
    *(uint2*)(d + 512) = lv;
}

// ---------------- mma.sync bf16 GEMM (unchanged from R4) ----------------
template <int MODE>
__global__ __launch_bounds__(256) void mma_gemm(const float* __restrict__ bias_ext,
                                                float* __restrict__ c_ext) {
    const __nv_bfloat16* A = (MODE == 0) ? g_a1 : g_a2;
    const __nv_bfloat16* W = (MODE == 0) ? g_wq : g_wp;
    const float* bias = (MODE == 0) ? g_qkvbias : bias_ext;
    float* C = (MODE == 0) ? g_qkv : c_ext;
    const int ldc = (MODE == 0) ? 768 : 256;

    extern __shared__ __align__(128) char smem[];
    const uint32_t sbase = smem_u32(smem);
    const int t = threadIdx.x;
    const int lane = t & 31, wid = t >> 5;
    const int bn = blockIdx.x * 128;
    const size_t bm = (size_t)blockIdx.y * 128;
    const int wm = (wid >> 2) * 64;
    const int wn = (wid & 3) * 32;

    const __nv_bfloat16* Ag = A + bm * 768;
    const __nv_bfloat16* Wg = W + (size_t)bn * 768;

    auto load_chunk = [&](int c, int s) {
        uint32_t ab = sbase + s * 32768;
        uint32_t bb = ab + 16384;
        const char* Ap = (const char*)(Ag + c * 64);
        const char* Bp = (const char*)(Wg + c * 64);
#pragma unroll
        for (int i = 0; i < 4; i++) {
            int u = i * 256 + t;
            int row = u >> 3;
            int c16 = u & 7;
            uint32_t off = (uint32_t)(row * 128 + ((c16 ^ (row & 7)) << 4));
            CP_ASYNC16(ab + off, Ap + (size_t)row * 1536 + c16 * 16);
            CP_ASYNC16(bb + off, Bp + (size_t)row * 1536 + c16 * 16);
        }
    };

    float acc[4][4][4];
#pragma unroll
    for (int mi = 0; mi < 4; mi++)
#pragma unroll
        for (int ni = 0; ni < 4; ni++)
#pragma unroll
            for (int q = 0; q < 4; q++) acc[mi][ni][q] = 0.0f;

    load_chunk(0, 0);
    CP_COMMIT();

    for (int c = 0; c < 12; c++) {
        if (c + 1 < 12) {
            load_chunk(c + 1, (c + 1) & 1);
            CP_COMMIT();
            CP_WAIT(1);
        } else {
            CP_WAIT(0);
        }
        __syncthreads();
        uint32_t ab = sbase + (c & 1) * 32768;
        uint32_t bb = ab + 16384;
#pragma unroll
        for (int ks = 0; ks < 4; ks++) {
            const int kc = ks * 2;
            uint32_t a_regs[4][4];
#pragma unroll
            for (int mi = 0; mi < 4; mi++) {
                int r = wm + mi * 16 + (lane & 15);
                int kk = kc + (lane >> 4);
                uint32_t addr = ab + r * 128 + ((kk ^ (r & 7)) << 4);
                LDSM_X4(a_regs[mi], addr);
            }
            uint32_t b_regs[2][4];
#pragma unroll
            for (int np = 0; np < 2; np++) {
                int r = wn + np * 16 + (lane & 15);
                int kk = kc + (lane >> 4);
                uint32_t addr = bb + r * 128 + ((kk ^ (r & 7)) << 4);
                LDSM_X4(b_regs[np], addr);
            }
#pragma unroll
            for (int mi = 0; mi < 4; mi++)
#pragma unroll
                for (int ni = 0; ni < 4; ni++) {
                    uint32_t b0 = b_regs[ni >> 1][ni & 1];
                    uint32_t b1 = b_regs[ni >> 1][(ni & 1) + 2];
                    MMA16816(acc[mi][ni], a_regs[mi], b0, b1);
                }
        }
        __syncthreads();
    }

    const int g = lane >> 2, tt = lane & 3;
#pragma unroll
    for (int mi = 0; mi < 4; mi++) {
        size_t r0 = bm + wm + mi * 16 + g;
#pragma unroll
        for (int ni = 0; ni < 4; ni++) {
            int col = bn + wn + ni * 8 + tt * 2;
            float bv0 = bias[col], bv1 = bias[col + 1];
            float2 v0 = make_float2(acc[mi][ni][0] + bv0, acc[mi][ni][1] + bv1);
            float2 v1 = make_float2(acc[mi][ni][2] + bv0, acc[mi][ni][3] + bv1);
            *(float2*)(C + r0 * ldc + col) = v0;
            *(float2*)(C + (r0 + 8) * ldc + col) = v1;
        }
    }
}

// ---------------- HMMA attention: one block (128 thr) per (window, head) ----
// smem layout (bytes):
//   [0, 9216)      sq32: q fp32, 64 rows x 36 floats   (later reused as sO)
//   [9216, 18432)  sk32: k fp32
//   [18432, 31744) q' bf16 [hi|lo|hi], 64 rows, pitch 208B (96 bf16 + pad)
//   [31744, 45056) k' bf16 [hi|hi|lo], 64 rows, pitch 208B
//   [45056, 49664) Vt hi bf16, 32 rows (d) x 64 (m), pitch 144B
//   [49664, 54272) Vt lo bf16
#define ATTN_SMEM 54272
__global__ __launch_bounds__(128) void attn_mma(const float* __restrict__ logit_scale) {
    extern __shared__ __align__(128) char smem[];
    const int b = blockIdx.x, h = blockIdx.y;
    const int t = threadIdx.x;
    const int lane = t & 31, w = t >> 5;
    const uint32_t sb = smem_u32(smem);

    float* sq32 = (float*)smem;
    float* sk32 = (float*)(smem + 9216);
    const float* base = g_qkv + (size_t)b * (64 * 768) + h * 32;

    // cooperative fp32 load of q,k (coalesced float4)
#pragma unroll
    for (int i = 0; i < 4; i++) {
        int idx = t + i * 128;      // 0..511
        int n = idx >> 3;
        int d4 = (idx & 7) << 2;
        const float* rb = base + n * 768 + d4;
        *(float4*)(sq32 + n * 36 + d4) = *(const float4*)(rb);
        *(float4*)(sk32 + n * 36 + d4) = *(const float4*)(rb + 256);
    }

    // V: load fp32, split, store transposed Vt[d][m] (hi/lo)
    {
        int m = t >> 1, dh = (t & 1) * 16;
        const float* vr = base + m * 768 + 512 + dh;
        char* vth = smem + 45056;
        char* vtl = smem + 49664;
#pragma unroll
        for (int i = 0; i < 16; i += 4) {
            float4 v4 = *(const float4*)(vr + i);
            float vv[4] = {v4.x, v4.y, v4.z, v4.w};
#pragma unroll
            for (int q = 0; q < 4; q++) {
                unsigned short hh, ll;
                split2(vv[q], hh, ll);
                int d = dh + i + q;
                *(unsigned short*)(vth + d * 144 + m * 2) = hh;
                *(unsigned short*)(vtl + d * 144 + m * 2) = ll;
            }
        }
    }
    __syncthreads();

    // normalize (q: fold logit scale), split to bf16 hi/lo, write q'/k'
    {
        int r = (t < 64) ? t : (t - 64);
        const float* row = (t < 64) ? (sq32 + r * 36) : (sk32 + r * 36);
        float s = 0.0f;
#pragma unroll
        for (int d = 0; d < 32; d++) s += row[d] * row[d];
        float inv = 1.0f / fmaxf(sqrtf(s), 1e-12f);
        if (t < 64) inv *= __expf(fminf(logit_scale[h], 4.6051702f));
        unsigned short hi[32], lo[32];
#pragma unroll
        for (int d = 0; d < 32; d++) split2(row[d] * inv, hi[d], lo[d]);
        char* dst = smem + ((t < 64) ? 18432 : 31744) + r * 208;
        const unsigned short* sec1 = (t < 64) ? lo : hi;  // q: [h|l|h], k: [h|h|l]
        const unsigned short* sec2 = (t < 64) ? hi : lo;
#pragma unroll
        for (int i = 0; i < 4; i++) {
            uint4 v;
            v.x = (uint32_t)hi[i*8+0] | ((uint32_t)hi[i*8+1] << 16);
            v.y = (uint32_t)hi[i*8+2] | ((uint32_t)hi[i*8+3] << 16);
            v.z = (uint32_t)hi[i*8+4] | ((uint32_t)hi[i*8+5] << 16);
            v.w = (uint32_t)hi[i*8+6] | ((uint32_t)hi[i*8+7] << 16);
            *(uint4*)(dst + i * 16) = v;
        }
#pragma unroll
        for (int i = 0; i < 4; i++) {
            uint4 v;
            v.x = (uint32_t)sec1[i*8+0] | ((uint32_t)sec1[i*8+1] << 16);
            v.y = (uint32_t)sec1[i*8+2] | ((uint32_t)sec1[i*8+3] << 16);
            v.z = (uint32_t)sec1[i*8+4] | ((uint32_t)sec1[i*8+5] << 16);
            v.w = (uint32_t)sec1[i*8+6] | ((uint32_t)sec1[i*8+7] << 16);
            *(uint4*)(dst + 64 + i * 16) = v;
        }
#pragma unroll
        for (int i = 0; i < 4; i++) {
            uint4 v;
            v.x = (uint32_t)sec2[i*8+0] | ((uint32_t)sec2[i*8+1] << 16);
            v.y = (uint32_t)sec2[i*8+2] | ((uint32_t)sec2[i*8+3] << 16);
            v.z = (uint32_t)sec2[i*8+4] | ((uint32_t)sec2[i*8+5] << 16);
            v.w = (uint32_t)sec2[i*8+6] | ((uint32_t)sec2[i*8+7] << 16);
            *(uint4*)(dst + 128 + i * 16) = v;
        }
    }
    __syncthreads();

    // ---- QK^T: S(16x64) per warp, K'=96 (split sections) ----
    const int R = w * 16;  // this warp's q rows
    const uint32_t qbase = sb + 18432;
    const uint32_t kbase = sb + 31744;
    float sacc[8][4];
#pragma unroll
    for (int j = 0; j < 8; j++)
#pragma unroll
        for (int q = 0; q < 4; q++) sacc[j][q] = 0.0f;

#pragma unroll
    for (int kk = 0; kk < 6; kk++) {
        uint32_t a[4];
        {
            int r = R + (lane & 15);
            int ch = 2 * kk + (lane >> 4);
            LDSM_X4(a, qbase + r * 208 + ch * 16);
        }
#pragma unroll
        for (int nt = 0; nt < 4; nt++) {
            uint32_t br[4];
            int r = nt * 16 + (lane & 15);
            int ch = 2 * kk + (lane >> 4);
            LDSM_X4(br, kbase + r * 208 + ch * 16);
            MMA16816(sacc[nt * 2 + 0], a, br[0], br[2]);
            MMA16816(sacc[nt * 2 + 1], a, br[1], br[3]);
        }
    }

    // ---- bias + softmax in C-register layout ----
    const int g = lane >> 2, tt = lane & 3;
    const float* bp = g_bias16 + ((h * 64 + R + g) * 64);
#pragma unroll
    for (int j = 0; j < 8; j++) {
        int col = j * 8 + tt * 2;
        sacc[j][0] += bp[col];
        sacc[j][1] += bp[col + 1];
        sacc[j][2] += bp[col + 512];
        sacc[j][3] += bp[col + 513];
    }
    float m0 = -1e30f, m1 = -1e30f;
#pragma unroll
    for (int j = 0; j < 8; j++) {
        m0 = fmaxf(m0, fmaxf(sacc[j][0], sacc[j][1]));
        m1 = fmaxf(m1, fmaxf(sacc[j][2], sacc[j][3]));
    }
    m0 = fmaxf(m0, __shfl_xor_sync(0xffffffffu, m0, 1));
    m0 = fmaxf(m0, __shfl_xor_sync(0xffffffffu, m0, 2));
    m1 = fmaxf(m1, __shfl_xor_sync(0xffffffffu, m1, 1));
    m1 = fmaxf(m1, __shfl_xor_sync(0xffffffffu, m1, 2));
    float s0 = 0.0f, s1 = 0.0f;
#pragma unroll
    for (int j = 0; j < 8; j++) {
        sacc[j][0] = __expf(sacc[j][0] - m0);
        sacc[j][1] = __expf(sacc[j][1] - m0);
        sacc[j][2] = __expf(sacc[j][2] - m1);
        sacc[j][3] = __expf(sacc[j][3] - m1);
        s0 += sacc[j][0] + sacc[j][1];
        s1 += sacc[j][2] + sacc[j][3];
    }
    s0 += __shfl_xor_sync(0xffffffffu, s0, 1);
    s0 += __shfl_xor_sync(0xffffffffu, s0, 2);
    s1 += __shfl_xor_sync(0xffffffffu, s1, 1);
    s1 += __shfl_xor_sync(0xffffffffu, s1, 2);
    float r0 = 1.0f / s0, r1 = 1.0f / s1;

    // ---- build P hi/lo B-fragments directly from registers ----
    uint32_t bh[8][2], bl[8][2];
#pragma unroll
    for (int j = 0; j < 8; j++) {
        float p0 = sacc[j][0] * r0, p1 = sacc[j][1] * r0;
        float p2 = sacc[j][2] * r1, p3 = sacc[j][3] * r1;
        unsigned short h0, l0, h1, l1, h2, l2, h3, l3;
        split2(p0, h0, l0); split2(p1, h1, l1);
        split2(p2, h2, l2); split2(p3, h3, l3);
        bh[j][0] = (uint32_t)h0 | ((uint32_t)h1 << 16);
        bl[j][0] = (uint32_t)l0 | ((uint32_t)l1 << 16);
        bh[j][1] = (uint32_t)h2 | ((uint32_t)h3 << 16);
        bl[j][1] = (uint32_t)l2 | ((uint32_t)l3 << 16);
    }

    // ---- O^T = V^T P^T: 3 passes (Vh*Ph + Vh*Pl + Vl*Ph) ----
    float oacc[2][2][4];
#pragma unroll
    for (int mt = 0; mt < 2; mt++)
#pragma unroll
        for (int nt = 0; nt < 2; nt++)
#pragma unroll
            for (int q = 0; q < 4; q++) oacc[mt][nt][q] = 0.0f;

#pragma unroll
    for (int pass = 0; pass < 3; pass++) {
        const uint32_t vbase = sb + ((pass == 2) ? 49664 : 45056);
        uint32_t (*B)[2] = (pass == 1) ? bl : bh;
#pragma unroll
        for (int mt = 0; mt < 2; mt++) {
#pragma unroll
            for (int s = 0; s < 4; s++) {
                uint32_t a[4];
                int r = mt * 16 + (lane & 15);
                int ch = 2 * s + (lane >> 4);
                LDSM_X4(a, vbase + r * 144 + ch * 16);
                MMA16816(oacc[mt][0], a, B[2 * s][0], B[2 * s + 1][0]);
                MMA16816(oacc[mt][1], a, B[2 * s][1], B[2 * s + 1][1]);
            }
        }
    }

    // ---- stage O (transpose back) into smem, then coalesced split write ----
    float* sO = (float*)smem;  // reuse sq32 region (64 x 36)
#pragma unroll
    for (int mt = 0; mt < 2; mt++)
#pragma unroll
        for (int nt = 0; nt < 2; nt++) {
            int qr = R + nt * 8 + tt * 2;
            int d = mt * 16 + g;
            sO[qr * 36 + d] = oacc[mt][nt][0];
            sO[(qr + 1) * 36 + d] = oacc[mt][nt][1];
            sO[qr * 36 + d + 8] = oacc[mt][nt][2];
            sO[(qr + 1) * 36 + d + 8] = oacc[mt][nt][3];
        }
    __syncthreads();

    {
        int qr = t >> 1, dh = (t & 1) * 16;
        const float* orow = sO + qr * 36 + dh;
        unsigned short hi[16], lo[16];
#pragma unroll
        for (int i = 0; i < 16; i++) split2(orow[i], hi[i], lo[i]);
        __nv_bfloat16* og = g_a2 + (size_t)(b * 64 + qr) * 768 + h * 32 + dh;
        uint4 hv0, hv1, lv0, lv1;
        hv0.x = (uint32_t)hi[0] | ((uint32_t)hi[1] << 16);
        hv0.y = (uint32_t)hi[2] | ((uint32_t)hi[3] << 16);
        hv0.z = (uint32_t)hi[4] | ((uint32_t)hi[5] << 16);
        hv0.w = (uint32_t)hi[6] | ((uint32_t)hi[7] << 16);
        hv1.x = (uint32_t)hi[8] | ((uint32_t)hi[9] << 16);
        hv1.y = (uint32_t)hi[10] | ((uint32_t)hi[11] << 16);
        hv1.z = (uint32_t)hi[12] | ((uint32_t)hi[13] << 16);
        hv1.w = (uint32_t)hi[14] | ((uint32_t)hi[15] << 16);
        lv0.x = (uint32_t)lo[0] | ((uint32_t)lo[1] << 16);
        lv0.y = (uint32_t)lo[2] | ((uint32_t)lo[3] << 16);
        lv0.z = (uint32_t)lo[4] | ((uint32_t)lo[5] << 16);
        lv0.w = (uint32_t)lo[6] | ((uint32_t)lo[7] << 16);
        lv1.x = (uint32_t)lo[8] | ((uint32_t)lo[9] << 16);
        lv1.y = (uint32_t)lo[10] | ((uint32_t)lo[11] << 16);
        lv1.z = (uint32_t)lo[12] | ((uint32_t)lo[13] << 16);
        lv1.w = (uint32_t)lo[14] | ((uint32_t)lo[15] << 16);
        *(uint4*)(og) = hv0;
        *(uint4*)(og + 8) = hv1;
        *(uint4*)(og + 256) = lv0;
        *(uint4*)(og + 264) = lv1;
        *(uint4*)(og + 512) = hv0;
        *(uint4*)(og + 520) = hv1;
    }
}

extern "C" void kernel_launch(void* const* d_in, const int* in_sizes, int n_in,
                              void* d_out, int out_size) {
    const float* x           = (const float*)d_in[0];
    const float* qkv_w       = (const float*)d_in[1];
    const float* q_bias      = (const float*)d_in[2];
    const float* v_bias      = (const float*)d_in[3];
    const float* logit_scale = (const float*)d_in[4];
    const float* cpb_w1      = (const float*)d_in[5];
    const float* cpb_b1      = (const float*)d_in[6];
    const float* cpb_w2      = (const float*)d_in[7];
    const float* proj_w      = (const float*)d_in[8];
    const float* proj_b      = (const float*)d_in[9];
    float* out = (float*)d_out;

    const int SMEM_BYTES = 2 * 32768;
    cudaFuncSetAttribute(mma_gemm<0>, cudaFuncAttributeMaxDynamicSharedMemorySize, SMEM_BYTES);
    cudaFuncSetAttribute(mma_gemm<1>, cudaFuncAttributeMaxDynamicSharedMemorySize, SMEM_BYTES);
    cudaFuncSetAttribute(attn_mma, cudaFuncAttributeMaxDynamicSharedMemorySize, ATTN_SMEM);

    prep_kernel<<<1, 256>>>(cpb_w1, cpb_b1, cpb_w2, q_bias, v_bias);
    split_act<<<M_TOTAL * 256 / 4 / 256, 256>>>(x);
    split_w<0><<<768 * 256 / 4 / 256, 256>>>(qkv_w);
    split_w<1><<<256 * 256 / 4 / 256, 256>>>(proj_w);
    mma_gemm<0><<<dim3(6, M_TOTAL / 128), 256, SMEM_BYTES>>>(nullptr, nullptr);
    attn_mma<<<dim3(2048, 8), 128, ATTN_SMEM>>>(logit_scale);
    mma_gemm<1><<<dim3(2, M_TOTAL / 128), 256, SMEM_BYTES>>>(proj_b, out);
}